// round 5
// baseline (speedup 1.0000x reference)
#include <cuda_runtime.h>

// RelationMultiHeadSelfAttention — algebraically collapsed.
// out = einsum('nhqk,nqhd->nqhd', attention, v): k appears only in attention,
// and softmax over k sums to 1  =>  out[n,q,h,d] = v_proj[n,q,h,d].
// => out = concat(cls, values) @ blockdiag8(Wv)^T @ W_out^T + b_out
//
// Kernel 1: M[e, h*64+d] = sum_i W_out[e, h*64+i] * Wv[i, d]   (512x512 fold)
// Kernel 2: out(1024x512) = Vcat(1024x512) @ M^T + b_out        (tiled fp32 GEMM)

#define EMBED 512
#define QLEN 256
#define NBATCH 4
#define NQ (NBATCH * QLEN)  // 1024

__device__ float g_M[EMBED * EMBED];  // 1 MB scratch (static device global: allowed)

__global__ __launch_bounds__(256) void combine_kernel(const float* __restrict__ W_out,
                                                      const float* __restrict__ Wv) {
    int idx = blockIdx.x * blockDim.x + threadIdx.x;  // e*512 + c
    int e = idx >> 9;
    int c = idx & 511;
    int h = c >> 6;
    int d = c & 63;
    const float* wo = W_out + e * EMBED + h * 64;  // broadcast within warp
    float acc = 0.f;
#pragma unroll
    for (int i = 0; i < 64; i++)
        acc = fmaf(wo[i], Wv[i * 64 + d], acc);  // Wv read coalesced over d
    g_M[idx] = acc;
}

// 64x64 output tile per block, BK=32, 256 threads, 4x4 register micro-tile.
__global__ __launch_bounds__(256) void out_gemm(
    const float* __restrict__ values,  // (4,255,512)
    const float* __restrict__ cls,     // (512)
    const float* __restrict__ b_out,   // (512)
    float* __restrict__ out)           // (1024,512)
{
    __shared__ float As[32][65];  // [k][m], pitch 65 -> conflict-free (65 mod 32 == 1)
    __shared__ float Bs[32][65];  // [k][n]

    const int r0 = blockIdx.y * 64;   // output row block (n*256+q)
    const int c0 = blockIdx.x * 64;   // output col block (embed)
    const int t  = threadIdx.x;
    const int tx = t & 15;            // 0..15 -> 4 cols each
    const int ty = t >> 4;            // 0..15 -> 4 rows each

    // Tile-load mapping: 64 rows x 32 k, float4 over k.
    // 256 threads * 8 elems = 2048 elems = 512 float4 loads -> 2 float4/thread.
    const int lrow = t >> 2;          // 0..63 (row within tile)
    const int lk4  = (t & 3) * 4;     // k offset within first half: 0,4,8,12
    // second load covers k offset +16

    float acc[4][4] = {};

    for (int k0 = 0; k0 < EMBED; k0 += 32) {
        // --- A tile: virtual Vcat rows r0..r0+63, cols k0..k0+31 ---
        {
            int r = r0 + lrow;
            int q = r & (QLEN - 1);
            int n = r >> 8;
            const float* base = (q == 0)
                ? cls
                : (values + (size_t)(n * (QLEN - 1) + (q - 1)) * EMBED);
#pragma unroll
            for (int half = 0; half < 2; half++) {
                int k = lk4 + half * 16;
                float4 va = *(const float4*)(base + k0 + k);
                As[k + 0][lrow] = va.x;
                As[k + 1][lrow] = va.y;
                As[k + 2][lrow] = va.z;
                As[k + 3][lrow] = va.w;
            }
        }
        // --- B tile: M rows c0..c0+63, cols k0..k0+31 ---
        {
            const float* base = g_M + (size_t)(c0 + lrow) * EMBED + k0;
#pragma unroll
            for (int half = 0; half < 2; half++) {
                int k = lk4 + half * 16;
                float4 vb = *(const float4*)(base + k);
                Bs[k + 0][lrow] = vb.x;
                Bs[k + 1][lrow] = vb.y;
                Bs[k + 2][lrow] = vb.z;
                Bs[k + 3][lrow] = vb.w;
            }
        }
        __syncthreads();

#pragma unroll
        for (int kk = 0; kk < 32; kk++) {
            float a[4], b[4];
#pragma unroll
            for (int u = 0; u < 4; u++) a[u] = As[kk][ty * 4 + u];
#pragma unroll
            for (int v = 0; v < 4; v++) b[v] = Bs[kk][tx * 4 + v];
#pragma unroll
            for (int u = 0; u < 4; u++)
#pragma unroll
                for (int v = 0; v < 4; v++)
                    acc[u][v] = fmaf(a[u], b[v], acc[u][v]);
        }
        __syncthreads();
    }

#pragma unroll
    for (int u = 0; u < 4; u++) {
        int r = r0 + ty * 4 + u;
#pragma unroll
        for (int v = 0; v < 4; v++) {
            int c = c0 + tx * 4 + v;
            out[r * EMBED + c] = acc[u][v] + b_out[c];
        }
    }
}

extern "C" void kernel_launch(void* const* d_in, const int* in_sizes, int n_in,
                              void* d_out, int out_size) {
    // metadata order: values, keys, query, mask, relation, cls_token, Wv, Wk, Wq, W_out, b_out
    const float* values = (const float*)d_in[0];
    const float* cls    = (const float*)d_in[5];
    const float* Wv     = (const float*)d_in[6];
    const float* W_out  = (const float*)d_in[9];
    const float* b_out  = (const float*)d_in[10];
    float* out = (float*)d_out;

    combine_kernel<<<(EMBED * EMBED) / 256, 256>>>(W_out, Wv);
    dim3 grid(EMBED / 64, NQ / 64);  // 8 x 16 = 128 blocks
    out_gemm<<<grid, 256>>>(values, cls, b_out, out);
}

// round 13
// speedup vs baseline: 1.1653x; 1.1653x over previous
#include <cuda_runtime.h>
#include <cstdint>

// RelationMultiHeadSelfAttention — algebraically collapsed.
// softmax over k sums to 1 => out = concat(cls, values) @ blockdiag8(Wv)^T @ W_out^T + b_out
//
// Kernel 1 (combine): M[e, h*64+d] = sum_i W_out[e, h*64+i] * Wv[i, d]
// Kernel 2 (out_gemm): out(1024x512) = Vcat(1024x512) @ M^T + b_out
//   - 64x64 tile, 256 threads, 4x4 micro-tile
//   - packed fma.rn.f32x2 (2x fp32 rate on sm_103a)
//   - XOR-swizzled [32][64] smem tiles -> aligned conflict-free LDS.128
//   - double-buffered, register-prefetched pipeline (one sync per k-tile)

#define EMBED 512
#define QLEN 256
#define NQ 1024

__device__ float g_M[EMBED * EMBED];  // 1 MB scratch (static device global: allowed)

__global__ __launch_bounds__(256) void combine_kernel(const float* __restrict__ W_out,
                                                      const float* __restrict__ Wv) {
    __shared__ float sWv[64 * 64];
    for (int i = threadIdx.x; i < 64 * 64; i += 256) sWv[i] = Wv[i];
    __syncthreads();
    int idx = blockIdx.x * 256 + threadIdx.x;  // e*512 + c
    int e = idx >> 9;
    int c = idx & 511;
    int h = c >> 6;
    int d = c & 63;
    const float4* wo = (const float4*)(W_out + e * EMBED + h * 64);
    float acc = 0.f;
#pragma unroll
    for (int i4 = 0; i4 < 16; i4++) {
        float4 w = wo[i4];
        acc = fmaf(w.x, sWv[(i4 * 4 + 0) * 64 + d], acc);
        acc = fmaf(w.y, sWv[(i4 * 4 + 1) * 64 + d], acc);
        acc = fmaf(w.z, sWv[(i4 * 4 + 2) * 64 + d], acc);
        acc = fmaf(w.w, sWv[(i4 * 4 + 3) * 64 + d], acc);
    }
    g_M[idx] = acc;
}

#define FMA2(acc, a, b) \
    asm("fma.rn.f32x2 %0, %1, %2, %0;" : "+l"(acc) : "l"(a), "l"(b))

// Store a float4 spanning k..k+3 at logical (k, row) with the compute-side swizzle.
// Swizzle: logical col-group g (=row>>2) lives at physical group g ^ ((k>>2)&3).
__device__ __forceinline__ void sts4(float (*S)[64], int kbase, int row, float4 v) {
    int s = (kbase >> 2) & 3;  // constant over the 4 stored k's
    int col = ((((row >> 2) ^ s)) << 2) + (row & 3);
    S[kbase + 0][col] = v.x;
    S[kbase + 1][col] = v.y;
    S[kbase + 2][col] = v.z;
    S[kbase + 3][col] = v.w;
}

__global__ __launch_bounds__(256) void out_gemm(
    const float* __restrict__ values,  // (4,255,512)
    const float* __restrict__ cls,     // (512)
    const float* __restrict__ b_out,   // (512)
    float* __restrict__ out)           // (1024,512)
{
    __shared__ __align__(16) float As[2][32][64];
    __shared__ __align__(16) float Bs[2][32][64];

    const int r0 = blockIdx.y * 64;
    const int c0 = blockIdx.x * 64;
    const int t = threadIdx.x;
    const int tx = t & 15;   // col group (4 cols)
    const int ty = t >> 4;   // row group (4 rows)
    const int lrow = t >> 2; // 0..63: tile row this thread loads
    const int lk4 = (t & 3) * 4;

    // Global row gather: virtual Vcat row r -> cls (q==0) or values row.
    int r = r0 + lrow;
    int q = r & (QLEN - 1);
    int n = r >> 8;
    const float* arow = (q == 0) ? cls
                                 : (values + (size_t)(n * (QLEN - 1) + (q - 1)) * EMBED);
    const float* brow = g_M + (size_t)(c0 + lrow) * EMBED;

    // Prefetch tile 0
    float4 pa0 = *(const float4*)(arow + lk4);
    float4 pa1 = *(const float4*)(arow + lk4 + 16);
    float4 pb0 = *(const float4*)(brow + lk4);
    float4 pb1 = *(const float4*)(brow + lk4 + 16);

    unsigned long long acc[4][2];
#pragma unroll
    for (int u = 0; u < 4; u++) { acc[u][0] = 0ull; acc[u][1] = 0ull; }

    sts4(As[0], lk4, lrow, pa0);
    sts4(As[0], lk4 + 16, lrow, pa1);
    sts4(Bs[0], lk4, lrow, pb0);
    sts4(Bs[0], lk4 + 16, lrow, pb1);
    __syncthreads();

    for (int kt = 0; kt < 16; kt++) {
        int cur = kt & 1;
        if (kt < 15) {  // prefetch next tile into registers (overlaps compute)
            const float* an = arow + (kt + 1) * 32;
            const float* bn = brow + (kt + 1) * 32;
            pa0 = *(const float4*)(an + lk4);
            pa1 = *(const float4*)(an + lk4 + 16);
            pb0 = *(const float4*)(bn + lk4);
            pb1 = *(const float4*)(bn + lk4 + 16);
        }
#pragma unroll
        for (int kk = 0; kk < 32; kk++) {
            int s = (kk >> 2) & 3;
            float4 a4 = *(const float4*)&As[cur][kk][(ty ^ s) << 2];
            ulonglong2 b2 = *(const ulonglong2*)&Bs[cur][kk][(tx ^ s) << 2];
            unsigned long long ax, ay, az, aw;
            asm("mov.b64 %0, {%1, %1};" : "=l"(ax) : "f"(a4.x));
            asm("mov.b64 %0, {%1, %1};" : "=l"(ay) : "f"(a4.y));
            asm("mov.b64 %0, {%1, %1};" : "=l"(az) : "f"(a4.z));
            asm("mov.b64 %0, {%1, %1};" : "=l"(aw) : "f"(a4.w));
            FMA2(acc[0][0], ax, b2.x); FMA2(acc[0][1], ax, b2.y);
            FMA2(acc[1][0], ay, b2.x); FMA2(acc[1][1], ay, b2.y);
            FMA2(acc[2][0], az, b2.x); FMA2(acc[2][1], az, b2.y);
            FMA2(acc[3][0], aw, b2.x); FMA2(acc[3][1], aw, b2.y);
        }
        if (kt < 15) {
            int nxt = cur ^ 1;
            sts4(As[nxt], lk4, lrow, pa0);
            sts4(As[nxt], lk4 + 16, lrow, pa1);
            sts4(Bs[nxt], lk4, lrow, pb0);
            sts4(Bs[nxt], lk4 + 16, lrow, pb1);
            __syncthreads();
        }
    }

    float4 bias = *(const float4*)(b_out + c0 + (tx << 2));
#pragma unroll
    for (int u = 0; u < 4; u++) {
        float lo0, hi0, lo1, hi1;
        asm("mov.b64 {%0, %1}, %2;" : "=f"(lo0), "=f"(hi0) : "l"(acc[u][0]));
        asm("mov.b64 {%0, %1}, %2;" : "=f"(lo1), "=f"(hi1) : "l"(acc[u][1]));
        float4 o;
        o.x = lo0 + bias.x;
        o.y = hi0 + bias.y;
        o.z = lo1 + bias.z;
        o.w = hi1 + bias.w;
        *(float4*)(out + (size_t)(r0 + (ty << 2) + u) * EMBED + c0 + (tx << 2)) = o;
    }
}

extern "C" void kernel_launch(void* const* d_in, const int* in_sizes, int n_in,
                              void* d_out, int out_size) {
    // metadata order: values, keys, query, mask, relation, cls_token, Wv, Wk, Wq, W_out, b_out
    const float* values = (const float*)d_in[0];
    const float* cls    = (const float*)d_in[5];
    const float* Wv     = (const float*)d_in[6];
    const float* W_out  = (const float*)d_in[9];
    const float* b_out  = (const float*)d_in[10];
    float* out = (float*)d_out;

    combine_kernel<<<(EMBED * EMBED) / 256, 256>>>(W_out, Wv);
    dim3 grid(EMBED / 64, NQ / 64);  // 8 x 16 = 128 blocks
    out_gemm<<<grid, 256>>>(values, cls, b_out, out);
}

// round 14
// speedup vs baseline: 1.3006x; 1.1160x over previous
#include <cuda_runtime.h>
#include <cstdint>

// Collapsed: out = concat(cls, values) @ blockdiag8(Wv)^T @ W_out^T + b_out
// K1 combine -> g_M.  K2 gemm_partial: 128x128 tiles, 8x8 micro (2x2 of proven
// 4x4 pattern at +64), FFMA2, XOR-swizzled LDS.128, 8-way K-split -> g_part.
// K3 reduce: out = sum(partials) + bias.

#define EMBED 512
#define QLEN 256
#define NQ 1024
#define KSPLIT 8
#define KSLICE (EMBED / KSPLIT)  // 64 -> 2 k-tiles of 32 per CTA

__device__ float g_M[EMBED * EMBED];              // 1 MB
__device__ float g_part[KSPLIT * NQ * EMBED];     // 16 MB partials

__global__ __launch_bounds__(256) void combine_kernel(const float* __restrict__ W_out,
                                                      const float* __restrict__ Wv) {
    __shared__ float sWv[64 * 64];
    for (int i = threadIdx.x; i < 64 * 64; i += 256) sWv[i] = Wv[i];
    __syncthreads();
    int idx = blockIdx.x * 256 + threadIdx.x;
    int e = idx >> 9;
    int c = idx & 511;
    int h = c >> 6;
    int d = c & 63;
    const float4* wo = (const float4*)(W_out + e * EMBED + h * 64);
    float acc = 0.f;
#pragma unroll
    for (int i4 = 0; i4 < 16; i4++) {
        float4 w = wo[i4];
        acc = fmaf(w.x, sWv[(i4 * 4 + 0) * 64 + d], acc);
        acc = fmaf(w.y, sWv[(i4 * 4 + 1) * 64 + d], acc);
        acc = fmaf(w.z, sWv[(i4 * 4 + 2) * 64 + d], acc);
        acc = fmaf(w.w, sWv[(i4 * 4 + 3) * 64 + d], acc);
    }
    g_M[idx] = acc;
}

#define FMA2(acc, a, b) \
    asm("fma.rn.f32x2 %0, %1, %2, %0;" : "+l"(acc) : "l"(a), "l"(b))
#define PACK2(dst, f) \
    asm("mov.b64 %0, {%1, %1};" : "=l"(dst) : "f"(f))
#define UNPACK2(lo, hi, src) \
    asm("mov.b64 {%0, %1}, %2;" : "=f"(lo), "=f"(hi) : "l"(src))

// Swizzled store into a [32 k][128 col] tile; cols split into two 64-halves,
// each using the hw-verified swizzle: phys group = (r>>2) ^ ((k>>2)&3).
__device__ __forceinline__ void sts4h(float* S, int kbase, int row128, float4 v) {
    int half = (row128 >> 6) << 6;  // 0 or 64
    int r = row128 & 63;
    int s = (kbase >> 2) & 3;
    int col = half + ((((r >> 2) ^ s)) << 2) + (r & 3);
    S[(kbase + 0) * 128 + col] = v.x;
    S[(kbase + 1) * 128 + col] = v.y;
    S[(kbase + 2) * 128 + col] = v.z;
    S[(kbase + 3) * 128 + col] = v.w;
}

__global__ __launch_bounds__(256, 2) void gemm_partial(
    const float* __restrict__ values,  // (4,255,512)
    const float* __restrict__ cls)     // (512)
{
    __shared__ __align__(16) float As[2][32 * 128];  // 16 KB each
    __shared__ __align__(16) float Bs[2][32 * 128];

    const int c0 = blockIdx.x * 128;      // 4 col blocks
    const int r0 = blockIdx.y * 128;      // 8 row blocks
    const int kz = blockIdx.z;            // 8 k slices
    const int kbase0 = kz * KSLICE;
    const int t = threadIdx.x;
    const int tx = t & 15;
    const int ty = t >> 4;
    const int lrow = t >> 2;              // 0..63
    const int lk4 = (t & 3) * 4;

    // Row gather for the two A row-halves this thread loads.
    const float* arow0;
    const float* arow1;
    {
        int r = r0 + lrow;
        int q = r & (QLEN - 1), n = r >> 8;
        arow0 = (q == 0) ? cls : (values + (size_t)(n * (QLEN - 1) + (q - 1)) * EMBED);
        r = r0 + lrow + 64;
        q = r & (QLEN - 1); n = r >> 8;
        arow1 = (q == 0) ? cls : (values + (size_t)(n * (QLEN - 1) + (q - 1)) * EMBED);
    }
    const float* brow0 = g_M + (size_t)(c0 + lrow) * EMBED;
    const float* brow1 = g_M + (size_t)(c0 + lrow + 64) * EMBED;

    // Prefetch k-tile 0 of this slice.
    float4 pa0 = *(const float4*)(arow0 + kbase0 + lk4);
    float4 pa1 = *(const float4*)(arow0 + kbase0 + lk4 + 16);
    float4 pa2 = *(const float4*)(arow1 + kbase0 + lk4);
    float4 pa3 = *(const float4*)(arow1 + kbase0 + lk4 + 16);
    float4 pb0 = *(const float4*)(brow0 + kbase0 + lk4);
    float4 pb1 = *(const float4*)(brow0 + kbase0 + lk4 + 16);
    float4 pb2 = *(const float4*)(brow1 + kbase0 + lk4);
    float4 pb3 = *(const float4*)(brow1 + kbase0 + lk4 + 16);

    unsigned long long acc[8][4];
#pragma unroll
    for (int u = 0; u < 8; u++)
#pragma unroll
        for (int v = 0; v < 4; v++) acc[u][v] = 0ull;

    sts4h(As[0], lk4, lrow, pa0);
    sts4h(As[0], lk4 + 16, lrow, pa1);
    sts4h(As[0], lk4, lrow + 64, pa2);
    sts4h(As[0], lk4 + 16, lrow + 64, pa3);
    sts4h(Bs[0], lk4, lrow, pb0);
    sts4h(Bs[0], lk4 + 16, lrow, pb1);
    sts4h(Bs[0], lk4, lrow + 64, pb2);
    sts4h(Bs[0], lk4 + 16, lrow + 64, pb3);
    __syncthreads();

#pragma unroll
    for (int kt = 0; kt < 2; kt++) {
        if (kt == 0) {  // prefetch second (last) k-tile
            int k1 = kbase0 + 32;
            pa0 = *(const float4*)(arow0 + k1 + lk4);
            pa1 = *(const float4*)(arow0 + k1 + lk4 + 16);
            pa2 = *(const float4*)(arow1 + k1 + lk4);
            pa3 = *(const float4*)(arow1 + k1 + lk4 + 16);
            pb0 = *(const float4*)(brow0 + k1 + lk4);
            pb1 = *(const float4*)(brow0 + k1 + lk4 + 16);
            pb2 = *(const float4*)(brow1 + k1 + lk4);
            pb3 = *(const float4*)(brow1 + k1 + lk4 + 16);
        }
#pragma unroll
        for (int kk = 0; kk < 32; kk++) {
            int s = (kk >> 2) & 3;
            const float* A = &As[kt][kk * 128];
            const float* B = &Bs[kt][kk * 128];
            float4 a0 = *(const float4*)&A[(ty ^ s) << 2];
            float4 a1 = *(const float4*)&A[64 + ((ty ^ s) << 2)];
            ulonglong2 b0 = *(const ulonglong2*)&B[(tx ^ s) << 2];
            ulonglong2 b1 = *(const ulonglong2*)&B[64 + ((tx ^ s) << 2)];
            unsigned long long ap[8];
            PACK2(ap[0], a0.x); PACK2(ap[1], a0.y); PACK2(ap[2], a0.z); PACK2(ap[3], a0.w);
            PACK2(ap[4], a1.x); PACK2(ap[5], a1.y); PACK2(ap[6], a1.z); PACK2(ap[7], a1.w);
#pragma unroll
            for (int u = 0; u < 8; u++) {
                FMA2(acc[u][0], ap[u], b0.x);
                FMA2(acc[u][1], ap[u], b0.y);
                FMA2(acc[u][2], ap[u], b1.x);
                FMA2(acc[u][3], ap[u], b1.y);
            }
        }
        if (kt == 0) {
            sts4h(As[1], lk4, lrow, pa0);
            sts4h(As[1], lk4 + 16, lrow, pa1);
            sts4h(As[1], lk4, lrow + 64, pa2);
            sts4h(As[1], lk4 + 16, lrow + 64, pa3);
            sts4h(Bs[1], lk4, lrow, pb0);
            sts4h(Bs[1], lk4 + 16, lrow, pb1);
            sts4h(Bs[1], lk4, lrow + 64, pb2);
            sts4h(Bs[1], lk4 + 16, lrow + 64, pb3);
            __syncthreads();
        }
    }

    // Write partials (no bias here).
    float* pbase = g_part + (size_t)kz * (NQ * EMBED);
#pragma unroll
    for (int u = 0; u < 8; u++) {
        int row = r0 + ((u < 4) ? (ty * 4 + u) : (64 + ty * 4 + (u - 4)));
        float lo, hi;
        float4 o;
        UNPACK2(lo, hi, acc[u][0]); o.x = lo; o.y = hi;
        UNPACK2(lo, hi, acc[u][1]); o.z = lo; o.w = hi;
        *(float4*)(pbase + (size_t)row * EMBED + c0 + tx * 4) = o;
        UNPACK2(lo, hi, acc[u][2]); o.x = lo; o.y = hi;
        UNPACK2(lo, hi, acc[u][3]); o.z = lo; o.w = hi;
        *(float4*)(pbase + (size_t)row * EMBED + c0 + 64 + tx * 4) = o;
    }
}

__global__ __launch_bounds__(256) void reduce_kernel(const float* __restrict__ b_out,
                                                     float* __restrict__ out) {
    int i4 = blockIdx.x * 256 + threadIdx.x;       // float4 index, 0..131071
    const float4* p = (const float4*)g_part;
    float4 s = p[i4];
#pragma unroll
    for (int k = 1; k < KSPLIT; k++) {
        float4 v = p[(size_t)k * (NQ * EMBED / 4) + i4];
        s.x += v.x; s.y += v.y; s.z += v.z; s.w += v.w;
    }
    float4 b = ((const float4*)b_out)[i4 & (EMBED / 4 - 1)];
    s.x += b.x; s.y += b.y; s.z += b.z; s.w += b.w;
    ((float4*)out)[i4] = s;
}

extern "C" void kernel_launch(void* const* d_in, const int* in_sizes, int n_in,
                              void* d_out, int out_size) {
    // order: values, keys, query, mask, relation, cls_token, Wv, Wk, Wq, W_out, b_out
    const float* values = (const float*)d_in[0];
    const float* cls    = (const float*)d_in[5];
    const float* Wv     = (const float*)d_in[6];
    const float* W_out  = (const float*)d_in[9];
    const float* b_out  = (const float*)d_in[10];
    float* out = (float*)d_out;

    combine_kernel<<<(EMBED * EMBED) / 256, 256>>>(W_out, Wv);
    dim3 grid(EMBED / 128, NQ / 128, KSPLIT);  // 4 x 8 x 8 = 256 CTAs
    gemm_partial<<<grid, 256>>>(values, cls);
    reduce_kernel<<<(NQ * EMBED / 4) / 256, 256>>>(b_out, out);
}